// round 12
// baseline (speedup 1.0000x reference)
#include <cuda_runtime.h>
#include <math.h>

#define BLOCK 256
#define CLUSTER 2
#define K 8                  // elements per thread (2048 per CTA)
#define NW (BLOCK / 32)      // 8 warps
#define FP_SCALE 65536.f     // 2^16 fixed-point scale

// sm_103 integer REDUX: single-instruction warp reductions.
__device__ __forceinline__ int redux_add_s32(int v) {
    int r;
    asm volatile("redux.sync.add.s32 %0, %1, 0xffffffff;" : "=r"(r) : "r"(v));
    return r;
}
__device__ __forceinline__ unsigned redux_max_u32(unsigned v) {
    unsigned r;
    asm volatile("redux.sync.max.u32 %0, %1, 0xffffffff;" : "=r"(r) : "r"(v));
    return r;
}
__device__ __forceinline__ unsigned redux_min_u32(unsigned v) {
    unsigned r;
    asm volatile("redux.sync.min.u32 %0, %1, 0xffffffff;" : "=r"(r) : "r"(v));
    return r;
}
__device__ __forceinline__ unsigned ctarank() {
    unsigned r;
    asm("mov.u32 %0, %%cluster_ctarank;" : "=r"(r));
    return r;
}

__global__ void __cluster_dims__(CLUSTER, 1, 1) __launch_bounds__(BLOCK, 1)
spectral_rank2_kernel(const float4* __restrict__ in4, float4* __restrict__ out4) {
    __shared__ int sA[NW], sB[NW];
    __shared__ unsigned sM[NW], sN[NW];
    __shared__ __align__(16) uint4 ctot;   // packed CTA totals {Sc,Ss,qmx,qmn}

    const int t = threadIdx.x;
    const int lane = t & 31, w = t >> 5;
    const unsigned rank = ctarank();
    const int base = rank * (BLOCK * K / 4);   // float4 offset of this CTA's half

    // ---- Phase 1: 2 x float4 loads + feature transform (2048 elems/CTA).
    // sigmoid(|x|)=1/(1+e), v~=e, e=exp(-|x|); direction (1,q)/sqrt(1+q^2),
    // q = e + e^2 > 0.
    float4 xa = in4[base + t];
    float4 xb = in4[base + t + BLOCK];
    float xs[K] = {xa.x, xa.y, xa.z, xa.w, xb.x, xb.y, xb.z, xb.w};
    float q[K], cw[K];
    float pc = 0.f, ps = 0.f;
    unsigned pqmx = 0u, pqmn = 0xffffffffu;
#pragma unroll
    for (int k = 0; k < K; k++) {
        float e  = __expf(-fabsf(xs[k]));
        float qq = fmaf(e, e, e);                  // q = e + e^2
        float c  = rsqrtf(fmaf(qq, qq, 1.f));
        q[k] = qq; cw[k] = c;
        pc += c;
        ps = fmaf(qq, c, ps);
        unsigned qb = __float_as_uint(qq);
        pqmx = max(pqmx, qb);
        pqmn = min(pqmn, qb);
    }

    // ---- Local reduction: warp REDUX -> smem -> warp0 REDUX -> packed total.
    {
        int ia = redux_add_s32(__float2int_rn(pc * FP_SCALE));
        int ib = redux_add_s32(__float2int_rn(ps * FP_SCALE));
        unsigned m = redux_max_u32(pqmx);
        unsigned n = redux_min_u32(pqmn);
        if (lane == 0) { sA[w] = ia; sB[w] = ib; sM[w] = m; sN[w] = n; }
    }
    __syncthreads();
    if (w == 0) {
        // 8 partials replicated 4x across the warp; REDUX gives 4x the CTA sum
        // (folded into the final 2^-18 constant). Max total: 4*2048*2^16 = 2^29.
        int ia = redux_add_s32(sA[lane & 7]);
        int ib = redux_add_s32(sB[lane & 7]);
        unsigned m = redux_max_u32(sM[lane & 7]);
        unsigned n = redux_min_u32(sN[lane & 7]);
        if (lane == 0) ctot = make_uint4((unsigned)ia, (unsigned)ib, m, n);
    }
    // ---- Cluster barrier: arrive (release: orders ctot write) + wait (acquire).
    asm volatile("barrier.cluster.arrive.aligned;" ::: "memory");
    asm volatile("barrier.cluster.wait.aligned;" ::: "memory");

    // ---- Combine own + peer CTA totals (one 16B DSMEM load).
    uint4 own = ctot;
    uint4 peer;
    {
        unsigned laddr;
        asm("{ .reg .u64 a; cvta.to.shared.u64 a, %1; cvt.u32.u64 %0, a; }"
            : "=r"(laddr) : "l"(&ctot));
        unsigned raddr;
        asm("mapa.shared::cluster.u32 %0, %1, %2;"
            : "=r"(raddr) : "r"(laddr), "r"(rank ^ 1u));
        asm volatile("ld.shared::cluster.v4.u32 {%0,%1,%2,%3}, [%4];"
                     : "=r"(peer.x), "=r"(peer.y), "=r"(peer.z), "=r"(peer.w)
                     : "r"(raddr));
    }
    const float Sc = (float)((int)own.x + (int)peer.x) * (0x1p-18f);
    const float Ss = (float)((int)own.y + (int)peer.y) * (0x1p-18f);
    const float qmx = __uint_as_float(max(own.z, peer.z));
    const float qmn = __uint_as_float(min(own.w, peer.w));

    // ---- Closed form (no further reductions): Gram Perron eigenvector is
    // exactly (Sc, Ss) -> Fiedler direction is the orthogonal complement
    // (al, be) = (-Ss, Sc). F(q) ∝ sin(θ-φ)/sqrt(cos(θ-φ)) is strictly
    // increasing in q -> extremes at qmn/qmx (same op sequence as per-element).
    const float al = -Ss, be = Sc;
    float Fe[2];
    float qe[2] = {qmn, qmx};
#pragma unroll
    for (int k = 0; k < 2; k++) {
        float c    = rsqrtf(fmaf(qe[k], qe[k], 1.f));
        float d    = fmaf(qe[k], Ss, Sc) * c;
        float cdis = c * rsqrtf(d);
        Fe[k] = fmaf(be, qe[k], al) * cdis;
    }
    float Fmn = Fe[0], Fmx = Fe[1];              // monotone increasing in q
    float pivot = (fabsf(Fmx) >= fabsf(Fmn)) ? Fmx : Fmn;
    float sgn = (pivot >= 0.f) ? 1.f : -1.f;
    float mn = (sgn > 0.f) ? Fmn : -Fmx;
    float mx = (sgn > 0.f) ? Fmx : -Fmn;
    float scale = __fdividef(1.f, mx - mn + 1e-10f);
    float a1 = sgn * scale, a0 = -mn * scale;
    const float alp = al * a1, bep = be * a1;    // out = (bep*q+alp)*cdis + a0

    // ---- Epilogue: per-element Fiedler value + fused normalize + store.
    float r[K];
#pragma unroll
    for (int k = 0; k < K; k++) {
        float d    = fmaf(q[k], Ss, Sc) * cw[k]; // degree
        float cdis = cw[k] * rsqrtf(d);
        float g    = fmaf(bep, q[k], alp);
        r[k] = fmaf(g, cdis, a0);
    }
    out4[base + t]         = make_float4(r[0], r[1], r[2], r[3]);
    out4[base + t + BLOCK] = make_float4(r[4], r[5], r[6], r[7]);
}

extern "C" void kernel_launch(void* const* d_in, const int* in_sizes, int n_in,
                              void* d_out, int out_size) {
    (void)in_sizes; (void)n_in; (void)out_size;
    const float4* in = (const float4*)d_in[0];
    float4* out = (float4*)d_out;
    spectral_rank2_kernel<<<CLUSTER, BLOCK>>>(in, out);
}